// round 9
// baseline (speedup 1.0000x reference)
#include <cuda_runtime.h>
#include <cuda_bf16.h>
#include <cstdint>

// Shapes
#define TT 512
#define BB 16
#define DM 512
#define NH 8
#define HD 64
#define DFF 2048
#define NROW (TT*BB)          // 8192
#define EPS_BN 1.28402541668774148407f  // exp(0.25)

// ---------------- scratch (device globals; no allocation allowed) ----------------
__device__ float g_x[NROW*DM];
__device__ float g_hid[NROW*DFF];
__device__ float g_qkv[NROW*3*DM];
__device__ float g_pospad[1024*DM];
__device__ float g_p[1024*DM];
__device__ float g_scores[128*512*512];   // (B*H, T, T) fp32
__device__ float g_qu[128*512*64];
__device__ float g_qv[128*512*64];
__device__ float g_kk[128*512*64];
__device__ float g_vt[128*64*512];        // (B*H, d, s) transposed V
__device__ float g_buf1[NROW*DM];
__device__ float g_buf2[NROW*DM];

// ================= helpers =================
__device__ __forceinline__ uint32_t f2tf32(float f) {
    uint32_t r;
    asm("cvt.rna.tf32.f32 %0, %1;" : "=r"(r) : "f"(f));
    return r;
}
__device__ __forceinline__ uint4 cvt4(float4 v) {
    return make_uint4(f2tf32(v.x), f2tf32(v.y), f2tf32(v.z), f2tf32(v.w));
}
__device__ __forceinline__ void mma_tf32(float* c, const uint32_t* a, const uint32_t* b) {
    asm volatile("mma.sync.aligned.m16n8k8.row.col.f32.tf32.tf32.f32 "
        "{%0,%1,%2,%3},{%4,%5,%6,%7},{%8,%9},{%0,%1,%2,%3};"
        : "+f"(c[0]), "+f"(c[1]), "+f"(c[2]), "+f"(c[3])
        : "r"(a[0]), "r"(a[1]), "r"(a[2]), "r"(a[3]), "r"(b[0]), "r"(b[1]));
}

// ---------------- TF32 tensor-core GEMM (dense layers) ----------------
// C[rows,M] = act(A[rows,K] @ W[M,K]^T + bias) (+res)
// CTA tile 128x256, 8 warps (2x4), warp tile 64x64, K staged 32, double buffered.
#define SA 36
#define ASZ (128*SA)
#define WSZ (256*SA)
#define BUFF (ASZ+WSZ)
#define GSM_BYTES (2*BUFF*4)  // 110592 bytes
__global__ __launch_bounds__(256, 1) void tf32_gemm(
    const float* __restrict__ A, const float* __restrict__ W,
    const float* __restrict__ bias, const float* __restrict__ res,
    float* __restrict__ C, int K, int M, int act)
{
    extern __shared__ uint32_t sm[];
    const int tid = threadIdx.x;
    const int lane = tid & 31, warp = tid >> 5;
    const int wr = warp >> 2, wn = warp & 3;
    const int g = lane >> 2, t = lane & 3;
    const long n0 = (long)blockIdx.y * 128;
    const long m0 = (long)blockIdx.x * 256;

    float acc[4][8][4];
#pragma unroll
    for (int i = 0; i < 4; i++)
#pragma unroll
        for (int j = 0; j < 8; j++)
#pragma unroll
            for (int q = 0; q < 4; q++) acc[i][j][q] = 0.f;

    int ar[4], ac[4], wrw[8], wc[8];
#pragma unroll
    for (int i = 0; i < 4; i++) { int idx = tid + i * 256; ar[i] = idx >> 3; ac[i] = (idx & 7) * 4; }
#pragma unroll
    for (int i = 0; i < 8; i++) { int idx = tid + i * 256; wrw[i] = idx >> 3; wc[i] = (idx & 7) * 4; }

    float4 pa[4], pw[8];
#pragma unroll
    for (int i = 0; i < 4; i++) pa[i] = *(const float4*)(A + (n0 + ar[i]) * K + ac[i]);
#pragma unroll
    for (int i = 0; i < 8; i++) pw[i] = *(const float4*)(W + (m0 + wrw[i]) * K + wc[i]);

#pragma unroll
    for (int i = 0; i < 4; i++) *(uint4*)&sm[ar[i] * SA + ac[i]] = cvt4(pa[i]);
#pragma unroll
    for (int i = 0; i < 8; i++) *(uint4*)&sm[ASZ + wrw[i] * SA + wc[i]] = cvt4(pw[i]);
    __syncthreads();

    const int ns = K >> 5;
    for (int s = 0; s < ns; s++) {
        const uint32_t* buf = sm + (s & 1) * BUFF;
        if (s + 1 < ns) {
            int col = (s + 1) * 32;
#pragma unroll
            for (int i = 0; i < 4; i++) pa[i] = *(const float4*)(A + (n0 + ar[i]) * K + col + ac[i]);
#pragma unroll
            for (int i = 0; i < 8; i++) pw[i] = *(const float4*)(W + (m0 + wrw[i]) * K + col + wc[i]);
        }
#pragma unroll
        for (int kb = 0; kb < 4; kb++) {
            const int ca = kb * 8 + t;
            uint32_t afr[4][4];
#pragma unroll
            for (int mt = 0; mt < 4; mt++) {
                int r0 = wr * 64 + mt * 16 + g;
                afr[mt][0] = buf[r0 * SA + ca];
                afr[mt][1] = buf[(r0 + 8) * SA + ca];
                afr[mt][2] = buf[r0 * SA + ca + 4];
                afr[mt][3] = buf[(r0 + 8) * SA + ca + 4];
            }
            uint32_t bfr[8][2];
#pragma unroll
            for (int nt = 0; nt < 8; nt++) {
                int n = wn * 64 + nt * 8 + g;
                bfr[nt][0] = buf[ASZ + n * SA + ca];
                bfr[nt][1] = buf[ASZ + n * SA + ca + 4];
            }
#pragma unroll
            for (int mt = 0; mt < 4; mt++)
#pragma unroll
                for (int nt = 0; nt < 8; nt++)
                    mma_tf32(acc[mt][nt], afr[mt], bfr[nt]);
        }
        if (s + 1 < ns) {
            uint32_t* nb = sm + ((s + 1) & 1) * BUFF;
#pragma unroll
            for (int i = 0; i < 4; i++) *(uint4*)&nb[ar[i] * SA + ac[i]] = cvt4(pa[i]);
#pragma unroll
            for (int i = 0; i < 8; i++) *(uint4*)&nb[ASZ + wrw[i] * SA + wc[i]] = cvt4(pw[i]);
        }
        __syncthreads();
    }

#pragma unroll
    for (int mt = 0; mt < 4; mt++) {
#pragma unroll
        for (int nt = 0; nt < 8; nt++) {
            long row0 = n0 + wr * 64 + mt * 16 + g;
            int col = (int)m0 + wn * 64 + nt * 8 + 2 * t;
            float b0 = bias ? bias[col] : 0.f;
            float b1 = bias ? bias[col + 1] : 0.f;
#pragma unroll
            for (int h = 0; h < 2; h++) {
                long row = row0 + h * 8;
                float v0 = acc[mt][nt][h * 2 + 0] + b0;
                float v1 = acc[mt][nt][h * 2 + 1] + b1;
                if (act) {
                    v0 = v0 / (1.f + __expf(1.f - v0));
                    v1 = v1 / (1.f + __expf(1.f - v1));
                }
                if (res) {
                    v0 += res[row * M + col];
                    v1 += res[row * M + col + 1];
                }
                *(float2*)(C + row * M + col) = make_float2(v0, v1);
            }
        }
    }
}

// ---------------- batched TF32 GEMM (ac scores) ----------------
__global__ __launch_bounds__(256, 1) void tf32_gemm_b(
    const float* __restrict__ A_, const float* __restrict__ W_,
    float* __restrict__ C_, int K, int M, int wld,
    long abatch, long wstride, int wmask, long cbatch)
{
    extern __shared__ uint32_t sm[];
    const int bz = blockIdx.z;
    const float* A = A_ + (long)bz * abatch;
    const float* W = W_ + (long)(bz & wmask) * wstride;
    float* C = C_ + (long)bz * cbatch;

    const int tid = threadIdx.x;
    const int lane = tid & 31, warp = tid >> 5;
    const int wr = warp >> 2, wn = warp & 3;
    const int g = lane >> 2, t = lane & 3;
    const long n0 = (long)blockIdx.y * 128;
    const long m0 = (long)blockIdx.x * 256;

    float acc[4][8][4];
#pragma unroll
    for (int i = 0; i < 4; i++)
#pragma unroll
        for (int j = 0; j < 8; j++)
#pragma unroll
            for (int q = 0; q < 4; q++) acc[i][j][q] = 0.f;

    int ar[4], ac[4], wrw[8], wc[8];
#pragma unroll
    for (int i = 0; i < 4; i++) { int idx = tid + i * 256; ar[i] = idx >> 3; ac[i] = (idx & 7) * 4; }
#pragma unroll
    for (int i = 0; i < 8; i++) { int idx = tid + i * 256; wrw[i] = idx >> 3; wc[i] = (idx & 7) * 4; }

    float4 pa[4], pw[8];
#pragma unroll
    for (int i = 0; i < 4; i++) pa[i] = *(const float4*)(A + (n0 + ar[i]) * K + ac[i]);
#pragma unroll
    for (int i = 0; i < 8; i++) pw[i] = *(const float4*)(W + (m0 + wrw[i]) * (long)wld + wc[i]);

#pragma unroll
    for (int i = 0; i < 4; i++) *(uint4*)&sm[ar[i] * SA + ac[i]] = cvt4(pa[i]);
#pragma unroll
    for (int i = 0; i < 8; i++) *(uint4*)&sm[ASZ + wrw[i] * SA + wc[i]] = cvt4(pw[i]);
    __syncthreads();

    const int ns = K >> 5;
    for (int s = 0; s < ns; s++) {
        const uint32_t* buf = sm + (s & 1) * BUFF;
        if (s + 1 < ns) {
            int col = (s + 1) * 32;
#pragma unroll
            for (int i = 0; i < 4; i++) pa[i] = *(const float4*)(A + (n0 + ar[i]) * K + col + ac[i]);
#pragma unroll
            for (int i = 0; i < 8; i++) pw[i] = *(const float4*)(W + (m0 + wrw[i]) * (long)wld + col + wc[i]);
        }
#pragma unroll
        for (int kb = 0; kb < 4; kb++) {
            const int ca = kb * 8 + t;
            uint32_t afr[4][4];
#pragma unroll
            for (int mt = 0; mt < 4; mt++) {
                int r0 = wr * 64 + mt * 16 + g;
                afr[mt][0] = buf[r0 * SA + ca];
                afr[mt][1] = buf[(r0 + 8) * SA + ca];
                afr[mt][2] = buf[r0 * SA + ca + 4];
                afr[mt][3] = buf[(r0 + 8) * SA + ca + 4];
            }
            uint32_t bfr[8][2];
#pragma unroll
            for (int nt = 0; nt < 8; nt++) {
                int n = wn * 64 + nt * 8 + g;
                bfr[nt][0] = buf[ASZ + n * SA + ca];
                bfr[nt][1] = buf[ASZ + n * SA + ca + 4];
            }
#pragma unroll
            for (int mt = 0; mt < 4; mt++)
#pragma unroll
                for (int nt = 0; nt < 8; nt++)
                    mma_tf32(acc[mt][nt], afr[mt], bfr[nt]);
        }
        if (s + 1 < ns) {
            uint32_t* nb = sm + ((s + 1) & 1) * BUFF;
#pragma unroll
            for (int i = 0; i < 4; i++) *(uint4*)&nb[ar[i] * SA + ac[i]] = cvt4(pa[i]);
#pragma unroll
            for (int i = 0; i < 8; i++) *(uint4*)&nb[ASZ + wrw[i] * SA + wc[i]] = cvt4(pw[i]);
        }
        __syncthreads();
    }

#pragma unroll
    for (int mt = 0; mt < 4; mt++) {
#pragma unroll
        for (int nt = 0; nt < 8; nt++) {
            long row0 = n0 + wr * 64 + mt * 16 + g;
            int col = (int)m0 + wn * 64 + nt * 8 + 2 * t;
#pragma unroll
            for (int h = 0; h < 2; h++) {
                long row = row0 + h * 8;
                *(float2*)(C + row * M + col) =
                    make_float2(acc[mt][nt][h * 2 + 0], acc[mt][nt][h * 2 + 1]);
            }
        }
    }
}

// ---------------- bd GEMM with fused rel-shift scatter-add into scores ----------------
// Per bh: full = qv_bh (512x64) @ p_h (1024x64, ld=512)^T; scores[t][p-511+t] += full[t][p].
__global__ __launch_bounds__(256, 1) void tf32_gemm_bd(
    const float* __restrict__ A_, const float* __restrict__ W_,
    float* __restrict__ scores)
{
    extern __shared__ uint32_t sm[];
    const int bz = blockIdx.z;
    const float* A = A_ + (long)bz * (512L * 64);
    const float* W = W_ + (long)(bz & 7) * 64;
    const int K = 64, wld = 512;

    const int tid = threadIdx.x;
    const int lane = tid & 31, warp = tid >> 5;
    const int wr = warp >> 2, wn = warp & 3;
    const int g = lane >> 2, t = lane & 3;
    const long n0 = (long)blockIdx.y * 128;
    const long m0 = (long)blockIdx.x * 256;

    float acc[4][8][4];
#pragma unroll
    for (int i = 0; i < 4; i++)
#pragma unroll
        for (int j = 0; j < 8; j++)
#pragma unroll
            for (int q = 0; q < 4; q++) acc[i][j][q] = 0.f;

    int ar[4], ac[4], wrw[8], wc[8];
#pragma unroll
    for (int i = 0; i < 4; i++) { int idx = tid + i * 256; ar[i] = idx >> 3; ac[i] = (idx & 7) * 4; }
#pragma unroll
    for (int i = 0; i < 8; i++) { int idx = tid + i * 256; wrw[i] = idx >> 3; wc[i] = (idx & 7) * 4; }

    float4 pa[4], pw[8];
#pragma unroll
    for (int i = 0; i < 4; i++) pa[i] = *(const float4*)(A + (n0 + ar[i]) * K + ac[i]);
#pragma unroll
    for (int i = 0; i < 8; i++) pw[i] = *(const float4*)(W + (m0 + wrw[i]) * (long)wld + wc[i]);

#pragma unroll
    for (int i = 0; i < 4; i++) *(uint4*)&sm[ar[i] * SA + ac[i]] = cvt4(pa[i]);
#pragma unroll
    for (int i = 0; i < 8; i++) *(uint4*)&sm[ASZ + wrw[i] * SA + wc[i]] = cvt4(pw[i]);
    __syncthreads();

    const int ns = K >> 5;   // 2
    for (int s = 0; s < ns; s++) {
        const uint32_t* buf = sm + (s & 1) * BUFF;
        if (s + 1 < ns) {
            int col = (s + 1) * 32;
#pragma unroll
            for (int i = 0; i < 4; i++) pa[i] = *(const float4*)(A + (n0 + ar[i]) * K + col + ac[i]);
#pragma unroll
            for (int i = 0; i < 8; i++) pw[i] = *(const float4*)(W + (m0 + wrw[i]) * (long)wld + col + wc[i]);
        }
#pragma unroll
        for (int kb = 0; kb < 4; kb++) {
            const int ca = kb * 8 + t;
            uint32_t afr[4][4];
#pragma unroll
            for (int mt = 0; mt < 4; mt++) {
                int r0 = wr * 64 + mt * 16 + g;
                afr[mt][0] = buf[r0 * SA + ca];
                afr[mt][1] = buf[(r0 + 8) * SA + ca];
                afr[mt][2] = buf[r0 * SA + ca + 4];
                afr[mt][3] = buf[(r0 + 8) * SA + ca + 4];
            }
            uint32_t bfr[8][2];
#pragma unroll
            for (int nt = 0; nt < 8; nt++) {
                int n = wn * 64 + nt * 8 + g;
                bfr[nt][0] = buf[ASZ + n * SA + ca];
                bfr[nt][1] = buf[ASZ + n * SA + ca + 4];
            }
#pragma unroll
            for (int mt = 0; mt < 4; mt++)
#pragma unroll
                for (int nt = 0; nt < 8; nt++)
                    mma_tf32(acc[mt][nt], afr[mt], bfr[nt]);
        }
        if (s + 1 < ns) {
            uint32_t* nb = sm + ((s + 1) & 1) * BUFF;
#pragma unroll
            for (int i = 0; i < 4; i++) *(uint4*)&nb[ar[i] * SA + ac[i]] = cvt4(pa[i]);
#pragma unroll
            for (int i = 0; i < 8; i++) *(uint4*)&nb[ASZ + wrw[i] * SA + wc[i]] = cvt4(pw[i]);
        }
        __syncthreads();
    }

    // scatter-add epilogue: s = p - 511 + t, unique per (t,s)
    float* S = scores + (long)bz * 512 * 512;
#pragma unroll
    for (int mt = 0; mt < 4; mt++) {
#pragma unroll
        for (int nt = 0; nt < 8; nt++) {
            int trow0 = (int)n0 + wr * 64 + mt * 16 + g;
            int p = (int)m0 + wn * 64 + nt * 8 + 2 * t;
#pragma unroll
            for (int h = 0; h < 2; h++) {
                int trow = trow0 + h * 8;
                int si = p - 511 + trow;
                float* Sr = S + (long)trow * 512;
                if ((unsigned)si < 512u)       Sr[si]     += acc[mt][nt][h * 2 + 0];
                if ((unsigned)(si + 1) < 512u) Sr[si + 1] += acc[mt][nt][h * 2 + 1];
            }
        }
    }
}

// ---------------- attn@V batched TF32 GEMM ----------------
// Per bh: O (512x64) = scores_bh (512x512) @ vt_bh (64x512)^T, O written with ldc=8192
// CTA tile 128(t) x 64(d), 8 warps 4x2, warp tile 32x32, K=512 staged 32.
#define SAV 36
#define AVA (128*SAV)
#define AVW (64*SAV)
#define AVBUFF (AVA+AVW)
#define AVSM_BYTES (2*AVBUFF*4)   // 55296
__global__ __launch_bounds__(256, 1) void tf32_gemm_av(
    const float* __restrict__ A_, const float* __restrict__ W_, float* __restrict__ C_)
{
    extern __shared__ uint32_t sm[];
    const int bz = blockIdx.z;
    const float* A = A_ + (long)bz * (512L * 512);
    const float* W = W_ + (long)bz * (64L * 512);
    float* C = C_ + (long)bz * 64;
    const int K = 512;

    const int tid = threadIdx.x;
    const int lane = tid & 31, warp = tid >> 5;
    const int wr = warp >> 1, wn = warp & 1;      // 4 x 2 warps, warp tile 32x32
    const int g = lane >> 2, t = lane & 3;
    const long n0 = (long)blockIdx.y * 128;

    float acc[2][4][4];
#pragma unroll
    for (int i = 0; i < 2; i++)
#pragma unroll
        for (int j = 0; j < 4; j++)
#pragma unroll
            for (int q = 0; q < 4; q++) acc[i][j][q] = 0.f;

    // A tile 128x32: 4 float4/thread; W tile 64x32: 2 float4/thread
    int ar[4], ac[4], wrw[2], wc[2];
#pragma unroll
    for (int i = 0; i < 4; i++) { int idx = tid + i * 256; ar[i] = idx >> 3; ac[i] = (idx & 7) * 4; }
#pragma unroll
    for (int i = 0; i < 2; i++) { int idx = tid + i * 256; wrw[i] = idx >> 3; wc[i] = (idx & 7) * 4; }

    float4 pa[4], pw[2];
#pragma unroll
    for (int i = 0; i < 4; i++) pa[i] = *(const float4*)(A + (n0 + ar[i]) * K + ac[i]);
#pragma unroll
    for (int i = 0; i < 2; i++) pw[i] = *(const float4*)(W + (long)wrw[i] * K + wc[i]);

#pragma unroll
    for (int i = 0; i < 4; i++) *(uint4*)&sm[ar[i] * SAV + ac[i]] = cvt4(pa[i]);
#pragma unroll
    for (int i = 0; i < 2; i++) *(uint4*)&sm[AVA + wrw[i] * SAV + wc[i]] = cvt4(pw[i]);
    __syncthreads();

    const int ns = K >> 5;   // 16
    for (int s = 0; s < ns; s++) {
        const uint32_t* buf = sm + (s & 1) * AVBUFF;
        if (s + 1 < ns) {
            int col = (s + 1) * 32;
#pragma unroll
            for (int i = 0; i < 4; i++) pa[i] = *(const float4*)(A + (n0 + ar[i]) * K + col + ac[i]);
#pragma unroll
            for (int i = 0; i < 2; i++) pw[i] = *(const float4*)(W + (long)wrw[i] * K + col + wc[i]);
        }
#pragma unroll
        for (int kb = 0; kb < 4; kb++) {
            const int ca = kb * 8 + t;
            uint32_t afr[2][4];
#pragma unroll
            for (int mt = 0; mt < 2; mt++) {
                int r0 = wr * 32 + mt * 16 + g;
                afr[mt][0] = buf[r0 * SAV + ca];
                afr[mt][1] = buf[(r0 + 8) * SAV + ca];
                afr[mt][2] = buf[r0 * SAV + ca + 4];
                afr[mt][3] = buf[(r0 + 8) * SAV + ca + 4];
            }
            uint32_t bfr[4][2];
#pragma unroll
            for (int nt = 0; nt < 4; nt++) {
                int n = wn * 32 + nt * 8 + g;
                bfr[nt][0] = buf[AVA + n * SAV + ca];
                bfr[nt][1] = buf[AVA + n * SAV + ca + 4];
            }
#pragma unroll
            for (int mt = 0; mt < 2; mt++)
#pragma unroll
                for (int nt = 0; nt < 4; nt++)
                    mma_tf32(acc[mt][nt], afr[mt], bfr[nt]);
        }
        if (s + 1 < ns) {
            uint32_t* nb = sm + ((s + 1) & 1) * AVBUFF;
#pragma unroll
            for (int i = 0; i < 4; i++) *(uint4*)&nb[ar[i] * SAV + ac[i]] = cvt4(pa[i]);
#pragma unroll
            for (int i = 0; i < 2; i++) *(uint4*)&nb[AVA + wrw[i] * SAV + wc[i]] = cvt4(pw[i]);
        }
        __syncthreads();
    }

#pragma unroll
    for (int mt = 0; mt < 2; mt++) {
#pragma unroll
        for (int nt = 0; nt < 4; nt++) {
            long row0 = n0 + wr * 32 + mt * 16 + g;
            int col = wn * 32 + nt * 8 + 2 * t;
#pragma unroll
            for (int h = 0; h < 2; h++) {
                long row = row0 + h * 8;
                *(float2*)(C + row * 8192 + col) =
                    make_float2(acc[mt][nt][h * 2 + 0], acc[mt][nt][h * 2 + 1]);
            }
        }
    }
}

// ---------------- pos_emb pad to 1024 rows ----------------
__global__ void pospad_kernel(const float* __restrict__ pe, float* __restrict__ out) {
    int idx = blockIdx.x * 256 + threadIdx.x;   // 1024*512
    out[idx] = (idx < 1023 * DM) ? pe[idx] : 0.f;
}

// ---------------- attention prep: qu/qv/kk in (bh, t, d) layout ----------------
__global__ void attnprep_kernel(const float* __restrict__ qkv,
                                const float* __restrict__ ub, const float* __restrict__ vb,
                                float* __restrict__ qu, float* __restrict__ qv,
                                float* __restrict__ kk) {
    int idx = blockIdx.x * 256 + threadIdx.x;    // 128*512*64
    int d = idx & 63;
    int t = (idx >> 6) & 511;
    int bh = idx >> 15;
    int b = bh >> 3, h = bh & 7;
    long base = ((long)t * BB + b) * (3 * DM) + h * HD + d;
    float q = qkv[base] * 0.125f;
    qu[idx] = q + ub[h * HD + d];
    qv[idx] = q + vb[h * HD + d];
    kk[idx] = qkv[base + DM];
}

// ---------------- V transpose: vt[bh][d][s] ----------------
__global__ __launch_bounds__(256) void vtrans_kernel(const float* __restrict__ qkv,
                                                     float* __restrict__ vt) {
    __shared__ float tile[64][65];
    int bh = blockIdx.y; int b = bh >> 3, h = bh & 7;
    int s0 = blockIdx.x * 64;
    int tid = threadIdx.x;
#pragma unroll
    for (int i = 0; i < 16; i++) {
        int idx = tid + i * 256;
        int s = idx >> 6, d = idx & 63;
        tile[s][d] = qkv[((long)(s0 + s) * BB + b) * (3 * DM) + 2 * DM + h * HD + d];
    }
    __syncthreads();
#pragma unroll
    for (int i = 0; i < 16; i++) {
        int idx = tid + i * 256;
        int d = idx >> 6, s = idx & 63;
        vt[((long)bh * 64 + d) * 512 + s0 + s] = tile[s][d];
    }
}

// ---------------- softmax over last dim (512), in place ----------------
__global__ __launch_bounds__(128) void softmax_kernel(float* __restrict__ scores) {
    long row = blockIdx.x;
    float* x = scores + row * TT;
    int tid = threadIdx.x;
    __shared__ float red[128];
    float v[4];
    float m = -1e30f;
#pragma unroll
    for (int i = 0; i < 4; i++) { v[i] = x[tid + i * 128]; m = fmaxf(m, v[i]); }
    red[tid] = m; __syncthreads();
    for (int s = 64; s > 0; s >>= 1) { if (tid < s) red[tid] = fmaxf(red[tid], red[tid + s]); __syncthreads(); }
    m = red[0];
    float sum = 0.f;
#pragma unroll
    for (int i = 0; i < 4; i++) { v[i] = __expf(v[i] - m); sum += v[i]; }
    __syncthreads();
    red[tid] = sum; __syncthreads();
    for (int s = 64; s > 0; s >>= 1) { if (tid < s) red[tid] += red[tid + s]; __syncthreads(); }
    float inv = 1.f / red[0];
#pragma unroll
    for (int i = 0; i < 4; i++) x[tid + i * 128] = v[i] * inv;
}

// ---------------- GLU over channel dim ----------------
__global__ void glu_kernel(const float* __restrict__ in, float* __restrict__ out) {
    int idx = blockIdx.x * 256 + threadIdx.x;      // NROW*512
    int row = idx >> 9, c = idx & 511;
    float a = in[row * 1024 + c], g = in[row * 1024 + 512 + c];
    out[idx] = a / (1.f + __expf(-g));
}

// ---------------- depthwise causal conv (K=31) + bias + double_swish ----------------
__global__ void dwconv_kernel(const float* __restrict__ x, const float* __restrict__ w,
                              const float* __restrict__ bias, float* __restrict__ out) {
    int idx = blockIdx.x * 256 + threadIdx.x;      // NROW*512
    int c = idx & 511;
    int tb = idx >> 9; int b = tb & 15; int t = tb >> 4;
    float acc = bias[c];
#pragma unroll
    for (int j = 0; j < 31; j++) {
        int tt = t - 30 + j;
        if (tt >= 0) acc += w[c * 31 + j] * x[(tt * BB + b) * DM + c];
    }
    out[idx] = acc / (1.f + __expf(1.f - acc));
}

// ---------------- BasicNorm ----------------
__global__ __launch_bounds__(128) void norm_kernel(const float* __restrict__ x, float* __restrict__ out) {
    int row = blockIdx.x; int tid = threadIdx.x;
    const float* xr = x + row * DM;
    __shared__ float red[128];
    float v[4]; float s = 0.f;
#pragma unroll
    for (int i = 0; i < 4; i++) { v[i] = xr[tid + i * 128]; s += v[i] * v[i]; }
    red[tid] = s; __syncthreads();
    for (int k = 64; k > 0; k >>= 1) { if (tid < k) red[tid] += red[tid + k]; __syncthreads(); }
    float scale = rsqrtf(red[0] * (1.f / DM) + EPS_BN);
#pragma unroll
    for (int i = 0; i < 4; i++) out[row * DM + tid + i * 128] = v[i] * scale;
}

// ---------------- launch ----------------
static void launch_gemm(const float* A, const float* W, const float* bias, const float* res,
                        float* C, int Nrows, int K, int M, int act) {
    cudaFuncSetAttribute(tf32_gemm, cudaFuncAttributeMaxDynamicSharedMemorySize, GSM_BYTES);
    tf32_gemm<<<dim3(M / 256, Nrows / 128), 256, GSM_BYTES>>>(A, W, bias, res, C, K, M, act);
}

extern "C" void kernel_launch(void* const* d_in, const int* in_sizes, int n_in,
                              void* d_out, int out_size) {
    const float* src        = (const float*)d_in[0];
    const float* pos_emb    = (const float*)d_in[1];
    const float* ffm_w1     = (const float*)d_in[2];
    const float* ffm_b1     = (const float*)d_in[3];
    const float* ffm_w2     = (const float*)d_in[4];
    const float* ffm_b2     = (const float*)d_in[5];
    const float* ff_w1      = (const float*)d_in[6];
    const float* ff_b1      = (const float*)d_in[7];
    const float* ff_w2      = (const float*)d_in[8];
    const float* ff_b2      = (const float*)d_in[9];
    const float* in_proj_w  = (const float*)d_in[10];
    const float* in_proj_b  = (const float*)d_in[11];
    const float* out_proj_w = (const float*)d_in[12];
    const float* out_proj_b = (const float*)d_in[13];
    const float* linear_pos_w = (const float*)d_in[14];
    const float* pos_bias_u = (const float*)d_in[15];
    const float* pos_bias_v = (const float*)d_in[16];
    const float* conv_pw1_w = (const float*)d_in[17];
    const float* conv_pw1_b = (const float*)d_in[18];
    const float* conv_dw_w  = (const float*)d_in[19];
    const float* conv_dw_b  = (const float*)d_in[20];
    const float* conv_pw2_w = (const float*)d_in[21];
    const float* conv_pw2_b = (const float*)d_in[22];

    float *x, *hid, *qkv, *pospad, *p, *scores, *qu, *qv, *kk, *vt, *buf1, *buf2;
    cudaGetSymbolAddress((void**)&x, g_x);
    cudaGetSymbolAddress((void**)&hid, g_hid);
    cudaGetSymbolAddress((void**)&qkv, g_qkv);
    cudaGetSymbolAddress((void**)&pospad, g_pospad);
    cudaGetSymbolAddress((void**)&p, g_p);
    cudaGetSymbolAddress((void**)&scores, g_scores);
    cudaGetSymbolAddress((void**)&qu, g_qu);
    cudaGetSymbolAddress((void**)&qv, g_qv);
    cudaGetSymbolAddress((void**)&kk, g_kk);
    cudaGetSymbolAddress((void**)&vt, g_vt);
    cudaGetSymbolAddress((void**)&buf1, g_buf1);
    cudaGetSymbolAddress((void**)&buf2, g_buf2);

    cudaFuncSetAttribute(tf32_gemm_b, cudaFuncAttributeMaxDynamicSharedMemorySize, GSM_BYTES);
    cudaFuncSetAttribute(tf32_gemm_bd, cudaFuncAttributeMaxDynamicSharedMemorySize, GSM_BYTES);
    cudaFuncSetAttribute(tf32_gemm_av, cudaFuncAttributeMaxDynamicSharedMemorySize, AVSM_BYTES);

    // 1. macaron FFW
    launch_gemm(src, ffm_w1, ffm_b1, nullptr, hid, NROW, DM, DFF, 1);
    launch_gemm(hid, ffm_w2, ffm_b2, src, x, NROW, DFF, DM, 0);

    // 2. attention projections
    launch_gemm(x, in_proj_w, in_proj_b, nullptr, qkv, NROW, DM, 3 * DM, 0);
    pospad_kernel<<<(1024 * DM) / 256, 256>>>(pos_emb, pospad);
    launch_gemm(pospad, linear_pos_w, nullptr, nullptr, p, 1024, DM, DM, 0);

    // 3. attention: prep -> ac GEMM -> bd GEMM (fused shift scatter) -> softmax -> attn@V GEMM
    attnprep_kernel<<<(128 * 512 * 64) / 256, 256>>>(qkv, pos_bias_u, pos_bias_v, qu, qv, kk);
    vtrans_kernel<<<dim3(8, 128), 256>>>(qkv, vt);
    // ac[bh] = qu_bh (512x64) @ kk_bh (512x64)^T -> scores
    tf32_gemm_b<<<dim3(2, 4, 128), 256, GSM_BYTES>>>(
        qu, kk, scores, 64, 512, 64, 512L * 64, 512L * 64, 0x7FFFFFFF, 512L * 512);
    // bd with fused rel-shift scatter-add into scores
    tf32_gemm_bd<<<dim3(4, 4, 128), 256, GSM_BYTES>>>(qv, p, scores);
    softmax_kernel<<<128 * TT, 128>>>(scores);
    // attn@V -> buf1 in (t*B, C) layout
    tf32_gemm_av<<<dim3(1, 4, 128), 256, AVSM_BYTES>>>(scores, vt, buf1);
    launch_gemm(buf1, out_proj_w, out_proj_b, x, x, NROW, DM, DM, 0);

    // 4. conv module
    launch_gemm(x, conv_pw1_w, conv_pw1_b, nullptr, hid, NROW, DM, 1024, 0);
    glu_kernel<<<(NROW * DM) / 256, 256>>>(hid, buf1);
    dwconv_kernel<<<(NROW * DM) / 256, 256>>>(buf1, conv_dw_w, conv_dw_b, buf2);
    launch_gemm(buf2, conv_pw2_w, conv_pw2_b, x, x, NROW, DM, DM, 0);

    // 5. second FFW
    launch_gemm(x, ff_w1, ff_b1, nullptr, hid, NROW, DM, DFF, 1);
    launch_gemm(hid, ff_w2, ff_b2, x, x, NROW, DFF, DM, 0);

    // 6. BasicNorm -> output
    norm_kernel<<<NROW, 128>>>(x, (float*)d_out);
}

// round 10
// speedup vs baseline: 1.5881x; 1.5881x over previous
#include <cuda_runtime.h>
#include <cuda_fp16.h>
#include <cuda_bf16.h>
#include <cstdint>

// Shapes
#define TT 512
#define BB 16
#define DM 512
#define NH 8
#define HD 64
#define DFF 2048
#define NROW (TT*BB)          // 8192
#define EPS_BN 1.28402541668774148407f  // exp(0.25)

// ---------------- scratch (device globals; no allocation allowed) ----------------
__device__ float g_x[NROW*DM];
__device__ float g_hid[NROW*DFF];
__device__ float g_qkv[NROW*3*DM];
__device__ float g_pospad[1024*DM];
__device__ float g_p[1024*DM];
__device__ float g_scores[128*512*512];   // (B*H, T, T) fp32
__device__ float g_bd[128L*512*1024];     // (B*H, T, 2T pad) rel-pos term
__device__ float g_qu[128*512*64];
__device__ float g_qv[128*512*64];
__device__ float g_kk[128*512*64];
__device__ float g_buf1[NROW*DM];
__device__ float g_buf2[NROW*DM];

// ================= helpers =================
__device__ __forceinline__ uint32_t f2tf32(float f) {
    uint32_t r;
    asm("cvt.rna.tf32.f32 %0, %1;" : "=r"(r) : "f"(f));
    return r;
}
__device__ __forceinline__ uint4 cvt4(float4 v) {
    return make_uint4(f2tf32(v.x), f2tf32(v.y), f2tf32(v.z), f2tf32(v.w));
}
__device__ __forceinline__ void mma_tf32(float* c, const uint32_t* a, const uint32_t* b) {
    asm volatile("mma.sync.aligned.m16n8k8.row.col.f32.tf32.tf32.f32 "
        "{%0,%1,%2,%3},{%4,%5,%6,%7},{%8,%9},{%0,%1,%2,%3};"
        : "+f"(c[0]), "+f"(c[1]), "+f"(c[2]), "+f"(c[3])
        : "r"(a[0]), "r"(a[1]), "r"(a[2]), "r"(a[3]), "r"(b[0]), "r"(b[1]));
}
__device__ __forceinline__ void mma_f16(float* c, const uint32_t* a, const uint32_t* b) {
    asm volatile("mma.sync.aligned.m16n8k16.row.col.f32.f16.f16.f32 "
        "{%0,%1,%2,%3},{%4,%5,%6,%7},{%8,%9},{%0,%1,%2,%3};"
        : "+f"(c[0]), "+f"(c[1]), "+f"(c[2]), "+f"(c[3])
        : "r"(a[0]), "r"(a[1]), "r"(a[2]), "r"(a[3]), "r"(b[0]), "r"(b[1]));
}
__device__ __forceinline__ uint32_t pack2(float x, float y) {
    __half2 h = __floats2half2_rn(x, y);
    return *(uint32_t*)&h;
}

// ---------------- FP16 tensor-core GEMM (dense layers) ----------------
// C[rows,M] = act(A[rows,K] @ W[M,K]^T + bias) (+res)
// CTA tile 128x256, 8 warps (2x4), warp tile 64x64, K staged 32 (2x k16 MMA blocks),
// double buffered. SMEM in half2 words, row stride SH=20 words (40 halfs) conflict-free.
#define SH 20
#define ASZh (128*SH)         // 2560 words
#define WSZh (256*SH)         // 5120 words
#define BUFFh (ASZh+WSZh)     // 7680 words
#define GSMh (2*BUFFh*4)      // 61440 bytes
__global__ __launch_bounds__(256, 1) void fp16_gemm(
    const float* __restrict__ A, const float* __restrict__ W,
    const float* __restrict__ bias, const float* __restrict__ res,
    float* __restrict__ C, int K, int M, int act)
{
    extern __shared__ uint32_t sm[];
    const int tid = threadIdx.x;
    const int lane = tid & 31, warp = tid >> 5;
    const int wr = warp >> 2, wn = warp & 3;     // 2 x 4 warps, warp tile 64x64
    const int g = lane >> 2, t = lane & 3;
    const long n0 = (long)blockIdx.y * 128;
    const long m0 = (long)blockIdx.x * 256;

    float acc[4][8][4];
#pragma unroll
    for (int i = 0; i < 4; i++)
#pragma unroll
        for (int j = 0; j < 8; j++)
#pragma unroll
            for (int q = 0; q < 4; q++) acc[i][j][q] = 0.f;

    // fill mapping: A tile 128x32 (4 float4/thread), W tile 256x32 (8 float4/thread)
    int ar[4], ac[4], wrw[8], wc[8];
#pragma unroll
    for (int i = 0; i < 4; i++) { int idx = tid + i * 256; ar[i] = idx >> 3; ac[i] = (idx & 7) * 4; }
#pragma unroll
    for (int i = 0; i < 8; i++) { int idx = tid + i * 256; wrw[i] = idx >> 3; wc[i] = (idx & 7) * 4; }

    float4 pa[4], pw[8];
#pragma unroll
    for (int i = 0; i < 4; i++) pa[i] = *(const float4*)(A + (n0 + ar[i]) * K + ac[i]);
#pragma unroll
    for (int i = 0; i < 8; i++) pw[i] = *(const float4*)(W + (m0 + wrw[i]) * K + wc[i]);

    // store stage 0 (pack fp32x4 -> half2x2, STS.64)
#pragma unroll
    for (int i = 0; i < 4; i++)
        *(uint2*)&sm[ar[i] * SH + (ac[i] >> 1)] =
            make_uint2(pack2(pa[i].x, pa[i].y), pack2(pa[i].z, pa[i].w));
#pragma unroll
    for (int i = 0; i < 8; i++)
        *(uint2*)&sm[ASZh + wrw[i] * SH + (wc[i] >> 1)] =
            make_uint2(pack2(pw[i].x, pw[i].y), pack2(pw[i].z, pw[i].w));
    __syncthreads();

    const int ns = K >> 5;
    for (int s = 0; s < ns; s++) {
        const uint32_t* buf = sm + (s & 1) * BUFFh;
        if (s + 1 < ns) {
            int col = (s + 1) * 32;
#pragma unroll
            for (int i = 0; i < 4; i++) pa[i] = *(const float4*)(A + (n0 + ar[i]) * K + col + ac[i]);
#pragma unroll
            for (int i = 0; i < 8; i++) pw[i] = *(const float4*)(W + (m0 + wrw[i]) * K + col + wc[i]);
        }
        // 2 k16 MMA blocks per stage
#pragma unroll
        for (int kb = 0; kb < 2; kb++) {
            const int cb = kb * 8 + t;
            uint32_t afr[4][4];
#pragma unroll
            for (int mt = 0; mt < 4; mt++) {
                int r0 = wr * 64 + mt * 16 + g;
                afr[mt][0] = buf[r0 * SH + cb];
                afr[mt][1] = buf[(r0 + 8) * SH + cb];
                afr[mt][2] = buf[r0 * SH + cb + 4];
                afr[mt][3] = buf[(r0 + 8) * SH + cb + 4];
            }
            uint32_t bfr[8][2];
#pragma unroll
            for (int nt = 0; nt < 8; nt++) {
                int n = wn * 64 + nt * 8 + g;
                bfr[nt][0] = buf[ASZh + n * SH + cb];
                bfr[nt][1] = buf[ASZh + n * SH + cb + 4];
            }
#pragma unroll
            for (int mt = 0; mt < 4; mt++)
#pragma unroll
                for (int nt = 0; nt < 8; nt++)
                    mma_f16(acc[mt][nt], afr[mt], bfr[nt]);
        }
        if (s + 1 < ns) {
            uint32_t* nb = sm + ((s + 1) & 1) * BUFFh;
#pragma unroll
            for (int i = 0; i < 4; i++)
                *(uint2*)&nb[ar[i] * SH + (ac[i] >> 1)] =
                    make_uint2(pack2(pa[i].x, pa[i].y), pack2(pa[i].z, pa[i].w));
#pragma unroll
            for (int i = 0; i < 8; i++)
                *(uint2*)&nb[ASZh + wrw[i] * SH + (wc[i] >> 1)] =
                    make_uint2(pack2(pw[i].x, pw[i].y), pack2(pw[i].z, pw[i].w));
        }
        __syncthreads();
    }

#pragma unroll
    for (int mt = 0; mt < 4; mt++) {
#pragma unroll
        for (int nt = 0; nt < 8; nt++) {
            long row0 = n0 + wr * 64 + mt * 16 + g;
            int col = (int)m0 + wn * 64 + nt * 8 + 2 * t;
            float b0 = bias ? bias[col] : 0.f;
            float b1 = bias ? bias[col + 1] : 0.f;
#pragma unroll
            for (int h = 0; h < 2; h++) {
                long row = row0 + h * 8;
                float v0 = acc[mt][nt][h * 2 + 0] + b0;
                float v1 = acc[mt][nt][h * 2 + 1] + b1;
                if (act) {
                    v0 = v0 / (1.f + __expf(1.f - v0));
                    v1 = v1 / (1.f + __expf(1.f - v1));
                }
                if (res) {
                    v0 += res[row * M + col];
                    v1 += res[row * M + col + 1];
                }
                *(float2*)(C + row * M + col) = make_float2(v0, v1);
            }
        }
    }
}

// ---------------- batched TF32 GEMM (attention ac / bd) ----------------
#define SA 36
#define ASZ (128*SA)
#define WSZ (256*SA)
#define BUFF (ASZ+WSZ)
#define GSM_BYTES (2*BUFF*4)  // 110592 bytes
__global__ __launch_bounds__(256, 1) void tf32_gemm_b(
    const float* __restrict__ A_, const float* __restrict__ W_,
    float* __restrict__ C_, int K, int M, int wld,
    long abatch, long wstride, int wmask, long cbatch)
{
    extern __shared__ uint32_t sm[];
    const int bz = blockIdx.z;
    const float* A = A_ + (long)bz * abatch;
    const float* W = W_ + (long)(bz & wmask) * wstride;
    float* C = C_ + (long)bz * cbatch;

    const int tid = threadIdx.x;
    const int lane = tid & 31, warp = tid >> 5;
    const int wr = warp >> 2, wn = warp & 3;
    const int g = lane >> 2, t = lane & 3;
    const long n0 = (long)blockIdx.y * 128;
    const long m0 = (long)blockIdx.x * 256;

    float acc[4][8][4];
#pragma unroll
    for (int i = 0; i < 4; i++)
#pragma unroll
        for (int j = 0; j < 8; j++)
#pragma unroll
            for (int q = 0; q < 4; q++) acc[i][j][q] = 0.f;

    int ar[4], ac[4], wrw[8], wc[8];
#pragma unroll
    for (int i = 0; i < 4; i++) { int idx = tid + i * 256; ar[i] = idx >> 3; ac[i] = (idx & 7) * 4; }
#pragma unroll
    for (int i = 0; i < 8; i++) { int idx = tid + i * 256; wrw[i] = idx >> 3; wc[i] = (idx & 7) * 4; }

    float4 pa[4], pw[8];
#pragma unroll
    for (int i = 0; i < 4; i++) pa[i] = *(const float4*)(A + (n0 + ar[i]) * K + ac[i]);
#pragma unroll
    for (int i = 0; i < 8; i++) pw[i] = *(const float4*)(W + (m0 + wrw[i]) * (long)wld + wc[i]);

#pragma unroll
    for (int i = 0; i < 4; i++) *(uint4*)&sm[ar[i] * SA + ac[i]] = cvt4(pa[i]);
#pragma unroll
    for (int i = 0; i < 8; i++) *(uint4*)&sm[ASZ + wrw[i] * SA + wc[i]] = cvt4(pw[i]);
    __syncthreads();

    const int ns = K >> 5;
    for (int s = 0; s < ns; s++) {
        const uint32_t* buf = sm + (s & 1) * BUFF;
        if (s + 1 < ns) {
            int col = (s + 1) * 32;
#pragma unroll
            for (int i = 0; i < 4; i++) pa[i] = *(const float4*)(A + (n0 + ar[i]) * K + col + ac[i]);
#pragma unroll
            for (int i = 0; i < 8; i++) pw[i] = *(const float4*)(W + (m0 + wrw[i]) * (long)wld + col + wc[i]);
        }
#pragma unroll
        for (int kb = 0; kb < 4; kb++) {
            const int ca = kb * 8 + t;
            uint32_t afr[4][4];
#pragma unroll
            for (int mt = 0; mt < 4; mt++) {
                int r0 = wr * 64 + mt * 16 + g;
                afr[mt][0] = buf[r0 * SA + ca];
                afr[mt][1] = buf[(r0 + 8) * SA + ca];
                afr[mt][2] = buf[r0 * SA + ca + 4];
                afr[mt][3] = buf[(r0 + 8) * SA + ca + 4];
            }
            uint32_t bfr[8][2];
#pragma unroll
            for (int nt = 0; nt < 8; nt++) {
                int n = wn * 64 + nt * 8 + g;
                bfr[nt][0] = buf[ASZ + n * SA + ca];
                bfr[nt][1] = buf[ASZ + n * SA + ca + 4];
            }
#pragma unroll
            for (int mt = 0; mt < 4; mt++)
#pragma unroll
                for (int nt = 0; nt < 8; nt++)
                    mma_tf32(acc[mt][nt], afr[mt], bfr[nt]);
        }
        if (s + 1 < ns) {
            uint32_t* nb = sm + ((s + 1) & 1) * BUFF;
#pragma unroll
            for (int i = 0; i < 4; i++) *(uint4*)&nb[ar[i] * SA + ac[i]] = cvt4(pa[i]);
#pragma unroll
            for (int i = 0; i < 8; i++) *(uint4*)&nb[ASZ + wrw[i] * SA + wc[i]] = cvt4(pw[i]);
        }
        __syncthreads();
    }

#pragma unroll
    for (int mt = 0; mt < 4; mt++) {
#pragma unroll
        for (int nt = 0; nt < 8; nt++) {
            long row0 = n0 + wr * 64 + mt * 16 + g;
            int col = (int)m0 + wn * 64 + nt * 8 + 2 * t;
#pragma unroll
            for (int h = 0; h < 2; h++) {
                long row = row0 + h * 8;
                *(float2*)(C + row * M + col) =
                    make_float2(acc[mt][nt][h * 2 + 0], acc[mt][nt][h * 2 + 1]);
            }
        }
    }
}

// ---------------- pos_emb pad to 1024 rows ----------------
__global__ void pospad_kernel(const float* __restrict__ pe, float* __restrict__ out) {
    int idx = blockIdx.x * 256 + threadIdx.x;   // 1024*512
    out[idx] = (idx < 1023 * DM) ? pe[idx] : 0.f;
}

// ---------------- attention prep: qu/qv/kk in (bh, t, d) layout ----------------
__global__ void attnprep_kernel(const float* __restrict__ qkv,
                                const float* __restrict__ ub, const float* __restrict__ vb,
                                float* __restrict__ qu, float* __restrict__ qv,
                                float* __restrict__ kk) {
    int idx = blockIdx.x * 256 + threadIdx.x;    // 128*512*64
    int d = idx & 63;
    int t = (idx >> 6) & 511;
    int bh = idx >> 15;
    int b = bh >> 3, h = bh & 7;
    long base = ((long)t * BB + b) * (3 * DM) + h * HD + d;
    float q = qkv[base] * 0.125f;
    qu[idx] = q + ub[h * HD + d];
    qv[idx] = q + vb[h * HD + d];
    kk[idx] = qkv[base + DM];
}

// ---------------- softmax with fused rel-shift gather, in place ----------------
__global__ __launch_bounds__(128) void softmax_bd_kernel(
    float* __restrict__ scores, const float* __restrict__ bd)
{
    long row = blockIdx.x;                        // bh*512 + t
    int t = (int)(row & 511);
    float* x = scores + row * TT;
    const float* bdr = bd + row * 1024 + (511 - t);
    int tid = threadIdx.x;
    __shared__ float red[128];
    float v[4];
    float m = -1e30f;
#pragma unroll
    for (int i = 0; i < 4; i++) {
        int s = tid + i * 128;
        v[i] = x[s] + bdr[s];
        m = fmaxf(m, v[i]);
    }
    red[tid] = m; __syncthreads();
    for (int s = 64; s > 0; s >>= 1) { if (tid < s) red[tid] = fmaxf(red[tid], red[tid + s]); __syncthreads(); }
    m = red[0];
    float sum = 0.f;
#pragma unroll
    for (int i = 0; i < 4; i++) { v[i] = __expf(v[i] - m); sum += v[i]; }
    __syncthreads();
    red[tid] = sum; __syncthreads();
    for (int s = 64; s > 0; s >>= 1) { if (tid < s) red[tid] += red[tid + s]; __syncthreads(); }
    float inv = 1.f / red[0];
#pragma unroll
    for (int i = 0; i < 4; i++) x[tid + i * 128] = v[i] * inv;
}

// ---------------- attn @ V -> (T*B, DM) layout ----------------
__global__ __launch_bounds__(256) void attnv_kernel(
    const float* __restrict__ scores, const float* __restrict__ qkv, float* __restrict__ out)
{
    __shared__ float sa[64][33], sv[32][65];
    int bh = blockIdx.y; int b = bh >> 3, h = bh & 7;
    int t0 = blockIdx.x * 64;
    int tid = threadIdx.x;
    int tx = tid & 15, ty = tid >> 4;
    float acc[4][4];
#pragma unroll
    for (int i = 0; i < 4; i++)
#pragma unroll
        for (int j = 0; j < 4; j++) acc[i][j] = 0.f;
    const float* S = scores + ((long)bh * TT + t0) * TT;
    for (int sblk = 0; sblk < TT; sblk += 32) {
#pragma unroll
        for (int i = 0; i < 8; i++) {
            int idx = tid + i * 256; int rr = idx >> 5; int cc = idx & 31;
            sa[rr][cc] = S[rr * TT + sblk + cc];
        }
#pragma unroll
        for (int i = 0; i < 8; i++) {
            int idx = tid + i * 256; int rr = idx >> 6; int dd = idx & 63;
            sv[rr][dd] = qkv[((sblk + rr) * BB + b) * (3 * DM) + 2 * DM + h * HD + dd];
        }
        __syncthreads();
#pragma unroll
        for (int s = 0; s < 32; s++) {
            float a[4], vv[4];
#pragma unroll
            for (int i = 0; i < 4; i++) a[i] = sa[ty * 4 + i][s];
#pragma unroll
            for (int j = 0; j < 4; j++) vv[j] = sv[s][tx * 4 + j];
#pragma unroll
            for (int i = 0; i < 4; i++)
#pragma unroll
                for (int j = 0; j < 4; j++) acc[i][j] += a[i] * vv[j];
        }
        __syncthreads();
    }
#pragma unroll
    for (int i = 0; i < 4; i++) {
        int t = t0 + ty * 4 + i;
#pragma unroll
        for (int j = 0; j < 4; j++) {
            int d = tx * 4 + j;
            out[(t * BB + b) * DM + h * HD + d] = acc[i][j];
        }
    }
}

// ---------------- GLU over channel dim ----------------
__global__ void glu_kernel(const float* __restrict__ in, float* __restrict__ out) {
    int idx = blockIdx.x * 256 + threadIdx.x;      // NROW*512
    int row = idx >> 9, c = idx & 511;
    float a = in[row * 1024 + c], g = in[row * 1024 + 512 + c];
    out[idx] = a / (1.f + __expf(-g));
}

// ---------------- depthwise causal conv (K=31) + bias + double_swish ----------------
__global__ void dwconv_kernel(const float* __restrict__ x, const float* __restrict__ w,
                              const float* __restrict__ bias, float* __restrict__ out) {
    int idx = blockIdx.x * 256 + threadIdx.x;      // NROW*512
    int c = idx & 511;
    int tb = idx >> 9; int b = tb & 15; int t = tb >> 4;
    float acc = bias[c];
#pragma unroll
    for (int j = 0; j < 31; j++) {
        int tt = t - 30 + j;
        if (tt >= 0) acc += w[c * 31 + j] * x[(tt * BB + b) * DM + c];
    }
    out[idx] = acc / (1.f + __expf(1.f - acc));
}

// ---------------- BasicNorm ----------------
__global__ __launch_bounds__(128) void norm_kernel(const float* __restrict__ x, float* __restrict__ out) {
    int row = blockIdx.x; int tid = threadIdx.x;
    const float* xr = x + row * DM;
    __shared__ float red[128];
    float v[4]; float s = 0.f;
#pragma unroll
    for (int i = 0; i < 4; i++) { v[i] = xr[tid + i * 128]; s += v[i] * v[i]; }
    red[tid] = s; __syncthreads();
    for (int k = 64; k > 0; k >>= 1) { if (tid < k) red[tid] += red[tid + k]; __syncthreads(); }
    float scale = rsqrtf(red[0] * (1.f / DM) + EPS_BN);
#pragma unroll
    for (int i = 0; i < 4; i++) out[row * DM + tid + i * 128] = v[i] * scale;
}

// ---------------- launch ----------------
static void launch_gemm(const float* A, const float* W, const float* bias, const float* res,
                        float* C, int Nrows, int K, int M, int act) {
    cudaFuncSetAttribute(fp16_gemm, cudaFuncAttributeMaxDynamicSharedMemorySize, GSMh);
    fp16_gemm<<<dim3(M / 256, Nrows / 128), 256, GSMh>>>(A, W, bias, res, C, K, M, act);
}

extern "C" void kernel_launch(void* const* d_in, const int* in_sizes, int n_in,
                              void* d_out, int out_size) {
    const float* src        = (const float*)d_in[0];
    const float* pos_emb    = (const float*)d_in[1];
    const float* ffm_w1     = (const float*)d_in[2];
    const float* ffm_b1     = (const float*)d_in[3];
    const float* ffm_w2     = (const float*)d_in[4];
    const float* ffm_b2     = (const float*)d_in[5];
    const float* ff_w1      = (const float*)d_in[6];
    const float* ff_b1      = (const float*)d_in[7];
    const float* ff_w2      = (const float*)d_in[8];
    const float* ff_b2      = (const float*)d_in[9];
    const float* in_proj_w  = (const float*)d_in[10];
    const float* in_proj_b  = (const float*)d_in[11];
    const float* out_proj_w = (const float*)d_in[12];
    const float* out_proj_b = (const float*)d_in[13];
    const float* linear_pos_w = (const float*)d_in[14];
    const float* pos_bias_u = (const float*)d_in[15];
    const float* pos_bias_v = (const float*)d_in[16];
    const float* conv_pw1_w = (const float*)d_in[17];
    const float* conv_pw1_b = (const float*)d_in[18];
    const float* conv_dw_w  = (const float*)d_in[19];
    const float* conv_dw_b  = (const float*)d_in[20];
    const float* conv_pw2_w = (const float*)d_in[21];
    const float* conv_pw2_b = (const float*)d_in[22];

    float *x, *hid, *qkv, *pospad, *p, *scores, *bd, *qu, *qv, *kk, *buf1, *buf2;
    cudaGetSymbolAddress((void**)&x, g_x);
    cudaGetSymbolAddress((void**)&hid, g_hid);
    cudaGetSymbolAddress((void**)&qkv, g_qkv);
    cudaGetSymbolAddress((void**)&pospad, g_pospad);
    cudaGetSymbolAddress((void**)&p, g_p);
    cudaGetSymbolAddress((void**)&scores, g_scores);
    cudaGetSymbolAddress((void**)&bd, g_bd);
    cudaGetSymbolAddress((void**)&qu, g_qu);
    cudaGetSymbolAddress((void**)&qv, g_qv);
    cudaGetSymbolAddress((void**)&kk, g_kk);
    cudaGetSymbolAddress((void**)&buf1, g_buf1);
    cudaGetSymbolAddress((void**)&buf2, g_buf2);

    cudaFuncSetAttribute(tf32_gemm_b, cudaFuncAttributeMaxDynamicSharedMemorySize, GSM_BYTES);

    // 1. macaron FFW
    launch_gemm(src, ffm_w1, ffm_b1, nullptr, hid, NROW, DM, DFF, 1);
    launch_gemm(hid, ffm_w2, ffm_b2, src, x, NROW, DFF, DM, 0);

    // 2. attention projections
    launch_gemm(x, in_proj_w, in_proj_b, nullptr, qkv, NROW, DM, 3 * DM, 0);
    pospad_kernel<<<(1024 * DM) / 256, 256>>>(pos_emb, pospad);
    launch_gemm(pospad, linear_pos_w, nullptr, nullptr, p, 1024, DM, DM, 0);

    // 3. attention: prep -> ac GEMM -> bd GEMM -> fused softmax -> attn@V
    attnprep_kernel<<<(128 * 512 * 64) / 256, 256>>>(qkv, pos_bias_u, pos_bias_v, qu, qv, kk);
    // ac[bh] = qu_bh (512x64) @ kk_bh (512x64)^T -> scores (bh,512,512)
    tf32_gemm_b<<<dim3(2, 4, 128), 256, GSM_BYTES>>>(
        qu, kk, scores, 64, 512, 64, 512L * 64, 512L * 64, 0x7FFFFFFF, 512L * 512);
    // bd[bh] = qv_bh (512x64) @ p_h (1024x64, ld=512)^T -> bd (bh,512,1024)
    tf32_gemm_b<<<dim3(4, 4, 128), 256, GSM_BYTES>>>(
        qv, p, bd, 64, 1024, DM, 512L * 64, 64L, 7, 512L * 1024);
    softmax_bd_kernel<<<128 * TT, 128>>>(scores, bd);
    attnv_kernel<<<dim3(TT / 64, 128), 256>>>(scores, qkv, buf1);
    launch_gemm(buf1, out_proj_w, out_proj_b, x, x, NROW, DM, DM, 0);

    // 4. conv module
    launch_gemm(x, conv_pw1_w, conv_pw1_b, nullptr, hid, NROW, DM, 1024, 0);
    glu_kernel<<<(NROW * DM) / 256, 256>>>(hid, buf1);
    dwconv_kernel<<<(NROW * DM) / 256, 256>>>(buf1, conv_dw_w, conv_dw_b, buf2);
    launch_gemm(buf2, conv_pw2_w, conv_pw2_b, x, x, NROW, DM, DM, 0);

    // 5. second FFW
    launch_gemm(x, ff_w1, ff_b1, nullptr, hid, NROW, DM, DFF, 1);
    launch_gemm(hid, ff_w2, ff_b2, x, x, NROW, DFF, DM, 0);

    // 6. BasicNorm -> output
    norm_kernel<<<NROW, 128>>>(x, (float*)d_out);
}